// round 1
// baseline (speedup 1.0000x reference)
#include <cuda_runtime.h>

#define Bsz  4
#define Tseq 2048
#define Cemb 1024
#define NH   16
#define HD   64
#define NTOK (Bsz * Tseq)   // 8192

// Scratch (static device globals — no runtime allocation)
__device__ float g_h[NTOK * Cemb];          // 32 MB  (LN output, reused for LN2)
__device__ float g_qkv[NTOK * 3 * Cemb];    // 96 MB
__device__ float g_y[NTOK * Cemb];          // 32 MB  (attention output)
__device__ float g_ff[NTOK * 4 * Cemb];     // 128 MB (FF1 output)

// ---------------------------------------------------------------------------
// LayerNorm: one block per row of 1024, 256 threads
// ---------------------------------------------------------------------------
__global__ __launch_bounds__(256) void ln_kernel(
    const float* __restrict__ x, const float* __restrict__ w,
    const float* __restrict__ b, float* __restrict__ out)
{
    __shared__ float red[64];
    int row = blockIdx.x;
    int tid = threadIdx.x;
    const float* xr = x + (size_t)row * Cemb;

    float v[4];
    float s = 0.f, s2 = 0.f;
#pragma unroll
    for (int i = 0; i < 4; i++) {
        v[i] = xr[i * 256 + tid];
        s  += v[i];
        s2 += v[i] * v[i];
    }
#pragma unroll
    for (int o = 16; o; o >>= 1) {
        s  += __shfl_xor_sync(~0u, s,  o);
        s2 += __shfl_xor_sync(~0u, s2, o);
    }
    int warp = tid >> 5, lane = tid & 31;
    if (lane == 0) { red[warp] = s; red[warp + 8] = s2; }
    __syncthreads();
    if (tid < 32) {
        float a  = (tid < 8) ? red[tid]     : 0.f;
        float a2 = (tid < 8) ? red[tid + 8] : 0.f;
#pragma unroll
        for (int o = 4; o; o >>= 1) {
            a  += __shfl_xor_sync(~0u, a,  o);
            a2 += __shfl_xor_sync(~0u, a2, o);
        }
        if (tid == 0) { red[0] = a; red[1] = a2; }
    }
    __syncthreads();
    float mean = red[0] * (1.f / Cemb);
    float var  = red[1] * (1.f / Cemb) - mean * mean;
    float rstd = rsqrtf(var + 1e-5f);
#pragma unroll
    for (int i = 0; i < 4; i++) {
        int c = i * 256 + tid;
        out[(size_t)row * Cemb + c] = (v[i] - mean) * rstd * w[c] + b[c];
    }
}

// ---------------------------------------------------------------------------
// SGEMM: C[M,N] = A[M,K] @ W[K,N] + bias (+relu) (+resid)
// BM=128, BN=128, BK=16, 256 threads, 8x8 per thread
// Requires M%128==0, N%128==0, K%16==0 (all shapes here satisfy this)
// ---------------------------------------------------------------------------
__global__ __launch_bounds__(256) void gemm_kernel(
    const float* __restrict__ A, const float* __restrict__ W,
    const float* __restrict__ bias, const float* resid,
    float* C, int M, int N, int K, int relu)
{
    __shared__ float As[16][128];
    __shared__ float Bs[16][128];

    int tid = threadIdx.x;
    int tx = tid & 15, ty = tid >> 4;
    int n0 = blockIdx.x * 128, m0 = blockIdx.y * 128;

    float acc[8][8];
#pragma unroll
    for (int i = 0; i < 8; i++)
#pragma unroll
        for (int j = 0; j < 8; j++) acc[i][j] = 0.f;

    int arow = tid >> 2, akf = tid & 3;   // A: 2 x (row, float4 along K)
    int bkr  = tid >> 5, bnf = tid & 31;  // B: 2 x (k-row, float4 along N)

    for (int k0 = 0; k0 < K; k0 += 16) {
#pragma unroll
        for (int h = 0; h < 2; h++) {
            int row = arow + h * 64;
            float4 va = *(const float4*)(A + (size_t)(m0 + row) * K + k0 + akf * 4);
            As[akf * 4 + 0][row] = va.x;
            As[akf * 4 + 1][row] = va.y;
            As[akf * 4 + 2][row] = va.z;
            As[akf * 4 + 3][row] = va.w;
        }
#pragma unroll
        for (int h = 0; h < 2; h++) {
            int kr = bkr + h * 8;
            *(float4*)&Bs[kr][bnf * 4] =
                *(const float4*)(W + (size_t)(k0 + kr) * N + n0 + bnf * 4);
        }
        __syncthreads();
#pragma unroll
        for (int kk = 0; kk < 16; kk++) {
            float a[8], b[8];
            *(float4*)(a)     = *(float4*)&As[kk][ty * 8];
            *(float4*)(a + 4) = *(float4*)&As[kk][ty * 8 + 4];
            *(float4*)(b)     = *(float4*)&Bs[kk][tx * 8];
            *(float4*)(b + 4) = *(float4*)&Bs[kk][tx * 8 + 4];
#pragma unroll
            for (int i = 0; i < 8; i++)
#pragma unroll
                for (int j = 0; j < 8; j++)
                    acc[i][j] += a[i] * b[j];
        }
        __syncthreads();
    }

#pragma unroll
    for (int i = 0; i < 8; i++) {
        int m = m0 + ty * 8 + i;
#pragma unroll
        for (int j = 0; j < 8; j++) {
            int n = n0 + tx * 8 + j;
            float c = acc[i][j] + bias[n];
            if (relu) c = fmaxf(c, 0.f);
            if (resid) c += resid[(size_t)m * N + n];
            C[(size_t)m * N + n] = c;
        }
    }
}

// ---------------------------------------------------------------------------
// Flash attention, fp32, online softmax.
// Grid: (T/64, NH, B). 256 threads = 64 rows x 4 "quad" lanes.
// BR=64 query rows, BC=32 key cols per tile.
// Thread (r, qd) owns score cols {qd+4c} and output dims {qd+4j}.
// scale = 1/sqrt(Cemb) = 1/32  (reference uses full embed dim!)
// ---------------------------------------------------------------------------
__global__ __launch_bounds__(256) void flash_kernel(
    const float* __restrict__ qkv, float* __restrict__ y)
{
    __shared__ float Qs[64][68];
    __shared__ float Ks[32][68];
    __shared__ float Vs[32][68];
    __shared__ float Ps[64][36];

    int tid = threadIdx.x;
    int qt = blockIdx.x, h = blockIdx.y, b = blockIdx.z;
    int r = tid >> 2, qd = tid & 3;
    int q0 = qt * 64;
    const float* base = qkv + (size_t)b * Tseq * 3 * Cemb;

    // Load Q tile (64 x 64)
    {
        int row = tid >> 2, f4 = tid & 3;
        const float4* src = (const float4*)(base + (size_t)(q0 + row) * 3072 + h * HD);
#pragma unroll
        for (int i = 0; i < 4; i++)
            *(float4*)&Qs[row][(f4 + 4 * i) * 4] = src[f4 + 4 * i];
    }

    float m_i = -1e30f, l_i = 0.f;
    float acc[16];
#pragma unroll
    for (int j = 0; j < 16; j++) acc[j] = 0.f;

    int ktmax = 2 * qt + 1;
    int krow = tid >> 3, kf8 = tid & 7;

    for (int kt = 0; kt <= ktmax; kt++) {
        __syncthreads();  // previous tile fully consumed (also covers Q load)
        {
            const float* kr_ = base + (size_t)(kt * 32 + krow) * 3072 + Cemb + h * HD;
            const float* vr_ = kr_ + Cemb;
            *(float4*)&Ks[krow][kf8 * 4]      = ((const float4*)kr_)[kf8];
            *(float4*)&Ks[krow][kf8 * 4 + 32] = ((const float4*)kr_)[kf8 + 8];
            *(float4*)&Vs[krow][kf8 * 4]      = ((const float4*)vr_)[kf8];
            *(float4*)&Vs[krow][kf8 * 4 + 32] = ((const float4*)vr_)[kf8 + 8];
        }
        __syncthreads();

        // Scores: thread computes 8 columns (strided by 4 for bank spread)
        float s[8];
#pragma unroll
        for (int c = 0; c < 8; c++) s[c] = 0.f;
        for (int k = 0; k < 64; k++) {
            float qv = Qs[r][k];
#pragma unroll
            for (int c = 0; c < 8; c++)
                s[c] += qv * Ks[qd + 4 * c][k];
        }

        float mt = -1e30f;
#pragma unroll
        for (int c = 0; c < 8; c++) {
            int kg = kt * 32 + qd + 4 * c;
            s[c] = (kg <= q0 + r) ? s[c] * 0.03125f : -1e30f;
            mt = fmaxf(mt, s[c]);
        }
        mt = fmaxf(mt, __shfl_xor_sync(~0u, mt, 1));
        mt = fmaxf(mt, __shfl_xor_sync(~0u, mt, 2));
        float m_new = fmaxf(m_i, mt);
        float corr  = __expf(m_i - m_new);

        float lsum = 0.f;
#pragma unroll
        for (int c = 0; c < 8; c++) {
            float p = __expf(s[c] - m_new);
            lsum += p;
            Ps[r][qd + 4 * c] = p;
        }
        lsum += __shfl_xor_sync(~0u, lsum, 1);
        lsum += __shfl_xor_sync(~0u, lsum, 2);
        l_i = l_i * corr + lsum;
        m_i = m_new;
#pragma unroll
        for (int j = 0; j < 16; j++) acc[j] *= corr;
        __syncwarp();  // Ps row written by 4 lanes of this warp

        // O += P @ V  (thread owns dims qd+4j of its row)
#pragma unroll 8
        for (int c = 0; c < 32; c++) {
            float p = Ps[r][c];
#pragma unroll
            for (int j = 0; j < 16; j++)
                acc[j] += p * Vs[c][qd + 4 * j];
        }
        __syncwarp();  // Ps reads done before next tile's writes
    }

    float inv = 1.f / l_i;
    float* yo = y + (size_t)(b * Tseq + q0 + r) * Cemb + h * HD + qd;
#pragma unroll
    for (int j = 0; j < 16; j++)
        yo[4 * j] = acc[j] * inv;
}

// ---------------------------------------------------------------------------
// Launch: 7 kernels, graph-capturable, no allocation.
// ---------------------------------------------------------------------------
extern "C" void kernel_launch(void* const* d_in, const int* in_sizes, int n_in,
                              void* d_out, int out_size)
{
    (void)in_sizes; (void)n_in; (void)out_size;
    const float* x      = (const float*)d_in[0];
    const float* ln1_w  = (const float*)d_in[1];
    const float* ln1_b  = (const float*)d_in[2];
    const float* qkv_w  = (const float*)d_in[3];
    const float* qkv_b  = (const float*)d_in[4];
    const float* proj_w = (const float*)d_in[5];
    const float* proj_b = (const float*)d_in[6];
    const float* ln2_w  = (const float*)d_in[7];
    const float* ln2_b  = (const float*)d_in[8];
    const float* ff_w1  = (const float*)d_in[9];
    const float* ff_b1  = (const float*)d_in[10];
    const float* ff_w2  = (const float*)d_in[11];
    const float* ff_b2  = (const float*)d_in[12];
    float* out = (float*)d_out;

    float *ph, *pqkv, *py, *pff;
    cudaGetSymbolAddress((void**)&ph,   g_h);
    cudaGetSymbolAddress((void**)&pqkv, g_qkv);
    cudaGetSymbolAddress((void**)&py,   g_y);
    cudaGetSymbolAddress((void**)&pff,  g_ff);

    // 1) h = LN1(x)
    ln_kernel<<<NTOK, 256>>>(x, ln1_w, ln1_b, ph);
    // 2) qkv = h @ qkv_w + qkv_b
    gemm_kernel<<<dim3(3072 / 128, NTOK / 128), 256>>>(
        ph, qkv_w, qkv_b, nullptr, pqkv, NTOK, 3072, 1024, 0);
    // 3) y = causal_attention(q, k, v)
    flash_kernel<<<dim3(Tseq / 64, NH, Bsz), 256>>>(pqkv, py);
    // 4) x2 = x + y @ proj_w + proj_b   -> d_out
    gemm_kernel<<<dim3(1024 / 128, NTOK / 128), 256>>>(
        py, proj_w, proj_b, x, out, NTOK, 1024, 1024, 0);
    // 5) h2 = LN2(x2)
    ln_kernel<<<NTOK, 256>>>(out, ln2_w, ln2_b, ph);
    // 6) ff = relu(h2 @ ff_w1 + ff_b1)
    gemm_kernel<<<dim3(4096 / 128, NTOK / 128), 256>>>(
        ph, ff_w1, ff_b1, nullptr, pff, NTOK, 4096, 1024, 1);
    // 7) out = x2 + ff @ ff_w2 + ff_b2
    gemm_kernel<<<dim3(1024 / 128, NTOK / 128), 256>>>(
        pff, ff_w2, ff_b2, out, out, NTOK, 1024, 4096, 0);
}

// round 3
// speedup vs baseline: 1.9195x; 1.9195x over previous
#include <cuda_runtime.h>
#include <cstdint>

#define Bsz  4
#define Tseq 2048
#define Cemb 1024
#define NH   16
#define HD   64
#define NTOK (Bsz * Tseq)   // 8192

// ---------------------------------------------------------------------------
// Scratch (static device globals — no runtime allocation)
// ---------------------------------------------------------------------------
__device__ float g_h[NTOK * Cemb];
__device__ float g_qkv[NTOK * 3 * Cemb];
__device__ float g_y[NTOK * Cemb];
__device__ float g_ff[NTOK * 4 * Cemb];
// Transposed weights (N-major rows, K contiguous) for mma.sync B operand
__device__ float g_wt_qkv[3 * Cemb * Cemb];
__device__ float g_wt_proj[Cemb * Cemb];
__device__ float g_wt_ff1[4 * Cemb * Cemb];
__device__ float g_wt_ff2[Cemb * 4 * Cemb];

// ---------------------------------------------------------------------------
// Helpers
// ---------------------------------------------------------------------------
__device__ __forceinline__ uint32_t smem_u32(const void* p) {
    uint32_t a;
    asm("{ .reg .u64 t; cvta.to.shared.u64 t, %1; cvt.u32.u64 %0, t; }"
        : "=r"(a) : "l"(p));
    return a;
}
__device__ __forceinline__ float to_tf32(float x) {
    float r; asm("cvt.rna.tf32.f32 %0, %1;" : "=f"(r) : "f"(x)); return r;
}

#define CP16(sa, gp) \
    asm volatile("cp.async.cg.shared.global [%0], [%1], 16;" :: "r"(sa), "l"(gp))
#define CP_COMMIT() asm volatile("cp.async.commit_group;" ::: "memory")
#define CP_WAIT(n)  asm volatile("cp.async.wait_group %0;" :: "n"(n) : "memory")

__device__ __forceinline__ void mma1688(float* c, const uint32_t* a, const uint32_t* b) {
    asm volatile(
        "mma.sync.aligned.m16n8k8.row.col.f32.tf32.tf32.f32 "
        "{%0,%1,%2,%3}, {%4,%5,%6,%7}, {%8,%9}, {%0,%1,%2,%3};"
        : "+f"(c[0]), "+f"(c[1]), "+f"(c[2]), "+f"(c[3])
        : "r"(a[0]), "r"(a[1]), "r"(a[2]), "r"(a[3]), "r"(b[0]), "r"(b[1]));
}

// ---------------------------------------------------------------------------
// Weight transpose: W[K,N] -> Wt[N,K] with tf32 rounding
// ---------------------------------------------------------------------------
__global__ __launch_bounds__(256) void transpose_kernel(
    const float* __restrict__ W, float* __restrict__ Wt, int K, int N)
{
    __shared__ float t[32][33];
    int k0 = blockIdx.x * 32, n0 = blockIdx.y * 32;
    int tx = threadIdx.x, ty = threadIdx.y;
#pragma unroll
    for (int i = 0; i < 4; i++)
        t[ty + i * 8][tx] = W[(size_t)(k0 + ty + i * 8) * N + n0 + tx];
    __syncthreads();
#pragma unroll
    for (int i = 0; i < 4; i++)
        Wt[(size_t)(n0 + ty + i * 8) * K + k0 + tx] = to_tf32(t[tx][ty + i * 8]);
}

// ---------------------------------------------------------------------------
// LayerNorm (tf32-rounded output; consumed only by GEMMs)
// ---------------------------------------------------------------------------
__global__ __launch_bounds__(256) void ln_kernel(
    const float* __restrict__ x, const float* __restrict__ w,
    const float* __restrict__ b, float* __restrict__ out)
{
    __shared__ float red[64];
    int row = blockIdx.x;
    int tid = threadIdx.x;
    const float* xr = x + (size_t)row * Cemb;

    float v[4];
    float s = 0.f, s2 = 0.f;
#pragma unroll
    for (int i = 0; i < 4; i++) {
        v[i] = xr[i * 256 + tid];
        s  += v[i];
        s2 += v[i] * v[i];
    }
#pragma unroll
    for (int o = 16; o; o >>= 1) {
        s  += __shfl_xor_sync(~0u, s,  o);
        s2 += __shfl_xor_sync(~0u, s2, o);
    }
    int warp = tid >> 5, lane = tid & 31;
    if (lane == 0) { red[warp] = s; red[warp + 8] = s2; }
    __syncthreads();
    if (tid < 32) {
        float a  = (tid < 8) ? red[tid]     : 0.f;
        float a2 = (tid < 8) ? red[tid + 8] : 0.f;
#pragma unroll
        for (int o = 4; o; o >>= 1) {
            a  += __shfl_xor_sync(~0u, a,  o);
            a2 += __shfl_xor_sync(~0u, a2, o);
        }
        if (tid == 0) { red[0] = a; red[1] = a2; }
    }
    __syncthreads();
    float mean = red[0] * (1.f / Cemb);
    float var  = red[1] * (1.f / Cemb) - mean * mean;
    float rstd = rsqrtf(var + 1e-5f);
#pragma unroll
    for (int i = 0; i < 4; i++) {
        int c = i * 256 + tid;
        out[(size_t)row * Cemb + c] = to_tf32((v[i] - mean) * rstd * w[c] + b[c]);
    }
}

// ---------------------------------------------------------------------------
// tf32 mma.sync GEMM: C[M,N] = A[M,K] @ Bt[N,K]^T + bias (+relu) (+resid)
// BM=128, BN=128, BK=32. 256 threads = 8 warps (2 along M x 4 along N),
// warp tile 64x32 = 4x4 m16n8k8 tiles. 3-stage cp.async pipeline.
// smem rows padded to 36 floats -> conflict-free mma fragment LDS.
// ---------------------------------------------------------------------------
#define BK 32
#define SSTRIDE 36
#define STAGE_BYTES (128 * SSTRIDE * 4)   // 18432
#define NSTAGE 3
#define GSMEM_BYTES (2 * NSTAGE * STAGE_BYTES)  // 110592

__global__ __launch_bounds__(256) void tgemm_kernel(
    const float* __restrict__ A, const float* __restrict__ Bt,
    const float* __restrict__ bias, const float* resid,
    float* __restrict__ C, int M, int N, int K, int relu)
{
    extern __shared__ char smem[];
    const uint32_t sb = smem_u32(smem);
    const uint32_t sb_B = sb + NSTAGE * STAGE_BYTES;

    int tid = threadIdx.x, wid = tid >> 5, lane = tid & 31;
    int warp_m = wid >> 2, warp_n = wid & 3;   // 2 x 4
    int g = lane >> 2, t = lane & 3;
    int n0 = blockIdx.x * 128, m0 = blockIdx.y * 128;

    float acc[4][4][4];
#pragma unroll
    for (int i = 0; i < 4; i++)
#pragma unroll
        for (int j = 0; j < 4; j++)
#pragma unroll
            for (int q = 0; q < 4; q++) acc[i][j][q] = 0.f;

    const int nk = K >> 5;  // BK=32 chunks

    // ---- loader lambda (stage s, chunk kc) ----
    auto load_stage = [&](int s, int kc) {
        int k0 = kc << 5;
#pragma unroll
        for (int i = 0; i < 4; i++) {
            int idx = tid + i * 256;
            int r = idx >> 3, c = (idx & 7) * 4;
            uint32_t so = (uint32_t)((r * SSTRIDE + c) * 4);
            CP16(sb   + s * STAGE_BYTES + so, A  + (size_t)(m0 + r) * K + k0 + c);
            CP16(sb_B + s * STAGE_BYTES + so, Bt + (size_t)(n0 + r) * K + k0 + c);
        }
        CP_COMMIT();
    };

    load_stage(0, 0);
    load_stage(1, 1);
    load_stage(2, 2);

    const uint32_t* Asm = (const uint32_t*)smem;
    const uint32_t* Bsm = (const uint32_t*)(smem + NSTAGE * STAGE_BYTES);
    const int arow = warp_m * 64 + g;
    const int brow = warp_n * 32 + g;

    for (int kc = 0; kc < nk; kc++) {
        int buf = kc % NSTAGE;
        CP_WAIT(2);
        __syncthreads();

        const uint32_t* As_ = Asm + buf * (STAGE_BYTES / 4);
        const uint32_t* Bs_ = Bsm + buf * (STAGE_BYTES / 4);
#pragma unroll
        for (int ks = 0; ks < 4; ks++) {
            int k = ks * 8;
            uint32_t a[4][4], b[4][2];
#pragma unroll
            for (int i = 0; i < 4; i++) {
                int r = (arow + i * 16) * SSTRIDE + k + t;
                a[i][0] = As_[r];
                a[i][1] = As_[r + 8 * SSTRIDE];
                a[i][2] = As_[r + 4];
                a[i][3] = As_[r + 8 * SSTRIDE + 4];
            }
#pragma unroll
            for (int j = 0; j < 4; j++) {
                int r = (brow + j * 8) * SSTRIDE + k + t;
                b[j][0] = Bs_[r];
                b[j][1] = Bs_[r + 4];
            }
#pragma unroll
            for (int i = 0; i < 4; i++)
#pragma unroll
                for (int j = 0; j < 4; j++)
                    mma1688(acc[i][j], a[i], b[j]);
        }
        __syncthreads();
        if (kc + NSTAGE < nk) load_stage(buf, kc + NSTAGE);
        else CP_COMMIT();   // keep group count aligned
    }

    // ---- epilogue ----
#pragma unroll
    for (int i = 0; i < 4; i++) {
        int m = m0 + warp_m * 64 + i * 16 + g;
#pragma unroll
        for (int j = 0; j < 4; j++) {
            int n = n0 + warp_n * 32 + j * 8 + t * 2;
            float b0 = bias[n], b1 = bias[n + 1];
            float v0 = acc[i][j][0] + b0, v1 = acc[i][j][1] + b1;
            float v2 = acc[i][j][2] + b0, v3 = acc[i][j][3] + b1;
            if (relu) {
                v0 = to_tf32(fmaxf(v0, 0.f)); v1 = to_tf32(fmaxf(v1, 0.f));
                v2 = to_tf32(fmaxf(v2, 0.f)); v3 = to_tf32(fmaxf(v3, 0.f));
            }
            size_t go0 = (size_t)m * N + n;
            size_t go1 = (size_t)(m + 8) * N + n;
            if (resid) {
                float2 r0 = *(const float2*)(resid + go0);
                float2 r1 = *(const float2*)(resid + go1);
                v0 += r0.x; v1 += r0.y; v2 += r1.x; v3 += r1.y;
            }
            *(float2*)(C + go0) = make_float2(v0, v1);
            *(float2*)(C + go1) = make_float2(v2, v3);
        }
    }
}

// ---------------------------------------------------------------------------
// Flash attention, fp32, online softmax (unchanged; tf32-rounds its output)
// ---------------------------------------------------------------------------
__global__ __launch_bounds__(256) void flash_kernel(
    const float* __restrict__ qkv, float* __restrict__ y)
{
    __shared__ float Qs[64][68];
    __shared__ float Ks[32][68];
    __shared__ float Vs[32][68];
    __shared__ float Ps[64][36];

    int tid = threadIdx.x;
    int qt = blockIdx.x, h = blockIdx.y, b = blockIdx.z;
    int r = tid >> 2, qd = tid & 3;
    int q0 = qt * 64;
    const float* base = qkv + (size_t)b * Tseq * 3 * Cemb;

    {
        int row = tid >> 2, f4 = tid & 3;
        const float4* src = (const float4*)(base + (size_t)(q0 + row) * 3072 + h * HD);
#pragma unroll
        for (int i = 0; i < 4; i++)
            *(float4*)&Qs[row][(f4 + 4 * i) * 4] = src[f4 + 4 * i];
    }

    float m_i = -1e30f, l_i = 0.f;
    float acc[16];
#pragma unroll
    for (int j = 0; j < 16; j++) acc[j] = 0.f;

    int ktmax = 2 * qt + 1;
    int krow = tid >> 3, kf8 = tid & 7;

    for (int kt = 0; kt <= ktmax; kt++) {
        __syncthreads();
        {
            const float* kr_ = base + (size_t)(kt * 32 + krow) * 3072 + Cemb + h * HD;
            const float* vr_ = kr_ + Cemb;
            *(float4*)&Ks[krow][kf8 * 4]      = ((const float4*)kr_)[kf8];
            *(float4*)&Ks[krow][kf8 * 4 + 32] = ((const float4*)kr_)[kf8 + 8];
            *(float4*)&Vs[krow][kf8 * 4]      = ((const float4*)vr_)[kf8];
            *(float4*)&Vs[krow][kf8 * 4 + 32] = ((const float4*)vr_)[kf8 + 8];
        }
        __syncthreads();

        float s[8];
#pragma unroll
        for (int c = 0; c < 8; c++) s[c] = 0.f;
        for (int k = 0; k < 64; k++) {
            float qv = Qs[r][k];
#pragma unroll
            for (int c = 0; c < 8; c++)
                s[c] += qv * Ks[qd + 4 * c][k];
        }

        float mt = -1e30f;
#pragma unroll
        for (int c = 0; c < 8; c++) {
            int kg = kt * 32 + qd + 4 * c;
            s[c] = (kg <= q0 + r) ? s[c] * 0.03125f : -1e30f;
            mt = fmaxf(mt, s[c]);
        }
        mt = fmaxf(mt, __shfl_xor_sync(~0u, mt, 1));
        mt = fmaxf(mt, __shfl_xor_sync(~0u, mt, 2));
        float m_new = fmaxf(m_i, mt);
        float corr  = __expf(m_i - m_new);

        float lsum = 0.f;
#pragma unroll
        for (int c = 0; c < 8; c++) {
            float p = __expf(s[c] - m_new);
            lsum += p;
            Ps[r][qd + 4 * c] = p;
        }
        lsum += __shfl_xor_sync(~0u, lsum, 1);
        lsum += __shfl_xor_sync(~0u, lsum, 2);
        l_i = l_i * corr + lsum;
        m_i = m_new;
#pragma unroll
        for (int j = 0; j < 16; j++) acc[j] *= corr;
        __syncwarp();

#pragma unroll 8
        for (int c = 0; c < 32; c++) {
            float p = Ps[r][c];
#pragma unroll
            for (int j = 0; j < 16; j++)
                acc[j] += p * Vs[c][qd + 4 * j];
        }
        __syncwarp();
    }

    float inv = 1.f / l_i;
    float* yo = y + (size_t)(b * Tseq + q0 + r) * Cemb + h * HD + qd;
#pragma unroll
    for (int j = 0; j < 16; j++)
        yo[4 * j] = to_tf32(acc[j] * inv);
}

// ---------------------------------------------------------------------------
// Launch
// ---------------------------------------------------------------------------
extern "C" void kernel_launch(void* const* d_in, const int* in_sizes, int n_in,
                              void* d_out, int out_size)
{
    (void)in_sizes; (void)n_in; (void)out_size;
    const float* x      = (const float*)d_in[0];
    const float* ln1_w  = (const float*)d_in[1];
    const float* ln1_b  = (const float*)d_in[2];
    const float* qkv_w  = (const float*)d_in[3];
    const float* qkv_b  = (const float*)d_in[4];
    const float* proj_w = (const float*)d_in[5];
    const float* proj_b = (const float*)d_in[6];
    const float* ln2_w  = (const float*)d_in[7];
    const float* ln2_b  = (const float*)d_in[8];
    const float* ff_w1  = (const float*)d_in[9];
    const float* ff_b1  = (const float*)d_in[10];
    const float* ff_w2  = (const float*)d_in[11];
    const float* ff_b2  = (const float*)d_in[12];
    float* out = (float*)d_out;

    float *ph, *pqkv, *py, *pff, *twq, *twp, *tw1, *tw2;
    cudaGetSymbolAddress((void**)&ph,   g_h);
    cudaGetSymbolAddress((void**)&pqkv, g_qkv);
    cudaGetSymbolAddress((void**)&py,   g_y);
    cudaGetSymbolAddress((void**)&pff,  g_ff);
    cudaGetSymbolAddress((void**)&twq,  g_wt_qkv);
    cudaGetSymbolAddress((void**)&twp,  g_wt_proj);
    cudaGetSymbolAddress((void**)&tw1,  g_wt_ff1);
    cudaGetSymbolAddress((void**)&tw2,  g_wt_ff2);

    cudaFuncSetAttribute(tgemm_kernel,
                         cudaFuncAttributeMaxDynamicSharedMemorySize, GSMEM_BYTES);

    dim3 tb(32, 8);
    transpose_kernel<<<dim3(Cemb / 32, 3 * Cemb / 32), tb>>>(qkv_w, twq, Cemb, 3 * Cemb);
    transpose_kernel<<<dim3(Cemb / 32, Cemb / 32),     tb>>>(proj_w, twp, Cemb, Cemb);
    transpose_kernel<<<dim3(Cemb / 32, 4 * Cemb / 32), tb>>>(ff_w1, tw1, Cemb, 4 * Cemb);
    transpose_kernel<<<dim3(4 * Cemb / 32, Cemb / 32), tb>>>(ff_w2, tw2, 4 * Cemb, Cemb);

    // 1) h = LN1(x)
    ln_kernel<<<NTOK, 256>>>(x, ln1_w, ln1_b, ph);
    // 2) qkv = h @ qkv_w + qkv_b
    tgemm_kernel<<<dim3(3072 / 128, NTOK / 128), 256, GSMEM_BYTES>>>(
        ph, twq, qkv_b, nullptr, pqkv, NTOK, 3072, 1024, 0);
    // 3) y = attention(q, k, v)
    flash_kernel<<<dim3(Tseq / 64, NH, Bsz), 256>>>(pqkv, py);
    // 4) x2 = x + y @ proj_w + proj_b
    tgemm_kernel<<<dim3(1024 / 128, NTOK / 128), 256, GSMEM_BYTES>>>(
        py, twp, proj_b, x, out, NTOK, 1024, 1024, 0);
    // 5) h2 = LN2(x2)
    ln_kernel<<<NTOK, 256>>>(out, ln2_w, ln2_b, ph);
    // 6) ff = relu(h2 @ ff_w1 + ff_b1)
    tgemm_kernel<<<dim3(4096 / 128, NTOK / 128), 256, GSMEM_BYTES>>>(
        ph, tw1, ff_b1, nullptr, pff, NTOK, 4096, 1024, 1);
    // 7) out = x2 + ff @ ff_w2 + ff_b2
    tgemm_kernel<<<dim3(1024 / 128, NTOK / 128), 256, GSMEM_BYTES>>>(
        pff, tw2, ff_b2, out, out, NTOK, 1024, 4096, 0);
}

// round 4
// speedup vs baseline: 3.8669x; 2.0146x over previous
#include <cuda_runtime.h>
#include <cstdint>

#define Bsz  4
#define Tseq 2048
#define Cemb 1024
#define NH   16
#define HD   64
#define NTOK (Bsz * Tseq)   // 8192

// ---------------------------------------------------------------------------
// Scratch (static device globals — no runtime allocation)
// ---------------------------------------------------------------------------
__device__ float g_h[NTOK * Cemb];
__device__ float g_qkv[NTOK * 3 * Cemb];
__device__ float g_y[NTOK * Cemb];
__device__ float g_ff[NTOK * 4 * Cemb];
__device__ float g_wt_qkv[3 * Cemb * Cemb];
__device__ float g_wt_proj[Cemb * Cemb];
__device__ float g_wt_ff1[4 * Cemb * Cemb];
__device__ float g_wt_ff2[Cemb * 4 * Cemb];

// ---------------------------------------------------------------------------
// Helpers
// ---------------------------------------------------------------------------
__device__ __forceinline__ uint32_t smem_u32(const void* p) {
    uint32_t a;
    asm("{ .reg .u64 t; cvta.to.shared.u64 t, %1; cvt.u32.u64 %0, t; }"
        : "=r"(a) : "l"(p));
    return a;
}
__device__ __forceinline__ float to_tf32(float x) {
    float r; asm("cvt.rna.tf32.f32 %0, %1;" : "=f"(r) : "f"(x)); return r;
}

#define CP16(sa, gp) \
    asm volatile("cp.async.cg.shared.global [%0], [%1], 16;" :: "r"(sa), "l"(gp))
#define CP_COMMIT() asm volatile("cp.async.commit_group;" ::: "memory")
#define CP_WAIT(n)  asm volatile("cp.async.wait_group %0;" :: "n"(n) : "memory")

__device__ __forceinline__ void mma1688(float* c, const uint32_t* a, const uint32_t* b) {
    asm volatile(
        "mma.sync.aligned.m16n8k8.row.col.f32.tf32.tf32.f32 "
        "{%0,%1,%2,%3}, {%4,%5,%6,%7}, {%8,%9}, {%0,%1,%2,%3};"
        : "+f"(c[0]), "+f"(c[1]), "+f"(c[2]), "+f"(c[3])
        : "r"(a[0]), "r"(a[1]), "r"(a[2]), "r"(a[3]), "r"(b[0]), "r"(b[1]));
}

// ---------------------------------------------------------------------------
// Weight transpose: W[K,N] -> Wt[N,K] with tf32 rounding
// ---------------------------------------------------------------------------
__global__ __launch_bounds__(256) void transpose_kernel(
    const float* __restrict__ W, float* __restrict__ Wt, int K, int N)
{
    __shared__ float t[32][33];
    int k0 = blockIdx.x * 32, n0 = blockIdx.y * 32;
    int tx = threadIdx.x, ty = threadIdx.y;
#pragma unroll
    for (int i = 0; i < 4; i++)
        t[ty + i * 8][tx] = W[(size_t)(k0 + ty + i * 8) * N + n0 + tx];
    __syncthreads();
#pragma unroll
    for (int i = 0; i < 4; i++)
        Wt[(size_t)(n0 + ty + i * 8) * K + k0 + tx] = to_tf32(t[tx][ty + i * 8]);
}

// ---------------------------------------------------------------------------
// LayerNorm (tf32-rounded output; consumed only by GEMMs)
// ---------------------------------------------------------------------------
__global__ __launch_bounds__(256) void ln_kernel(
    const float* __restrict__ x, const float* __restrict__ w,
    const float* __restrict__ b, float* __restrict__ out)
{
    __shared__ float red[64];
    int row = blockIdx.x;
    int tid = threadIdx.x;
    const float* xr = x + (size_t)row * Cemb;

    float v[4];
    float s = 0.f, s2 = 0.f;
#pragma unroll
    for (int i = 0; i < 4; i++) {
        v[i] = xr[i * 256 + tid];
        s  += v[i];
        s2 += v[i] * v[i];
    }
#pragma unroll
    for (int o = 16; o; o >>= 1) {
        s  += __shfl_xor_sync(~0u, s,  o);
        s2 += __shfl_xor_sync(~0u, s2, o);
    }
    int warp = tid >> 5, lane = tid & 31;
    if (lane == 0) { red[warp] = s; red[warp + 8] = s2; }
    __syncthreads();
    if (tid < 32) {
        float a  = (tid < 8) ? red[tid]     : 0.f;
        float a2 = (tid < 8) ? red[tid + 8] : 0.f;
#pragma unroll
        for (int o = 4; o; o >>= 1) {
            a  += __shfl_xor_sync(~0u, a,  o);
            a2 += __shfl_xor_sync(~0u, a2, o);
        }
        if (tid == 0) { red[0] = a; red[1] = a2; }
    }
    __syncthreads();
    float mean = red[0] * (1.f / Cemb);
    float var  = red[1] * (1.f / Cemb) - mean * mean;
    float rstd = rsqrtf(var + 1e-5f);
#pragma unroll
    for (int i = 0; i < 4; i++) {
        int c = i * 256 + tid;
        out[(size_t)row * Cemb + c] = to_tf32((v[i] - mean) * rstd * w[c] + b[c]);
    }
}

// ---------------------------------------------------------------------------
// tf32 mma.sync GEMM (unchanged from R3)
// ---------------------------------------------------------------------------
#define BK 32
#define SSTRIDE 36
#define STAGE_BYTES (128 * SSTRIDE * 4)   // 18432
#define NSTAGE 3
#define GSMEM_BYTES (2 * NSTAGE * STAGE_BYTES)  // 110592

__global__ __launch_bounds__(256) void tgemm_kernel(
    const float* __restrict__ A, const float* __restrict__ Bt,
    const float* __restrict__ bias, const float* resid,
    float* __restrict__ C, int M, int N, int K, int relu)
{
    extern __shared__ char smem[];
    const uint32_t sb = smem_u32(smem);
    const uint32_t sb_B = sb + NSTAGE * STAGE_BYTES;

    int tid = threadIdx.x, wid = tid >> 5, lane = tid & 31;
    int warp_m = wid >> 2, warp_n = wid & 3;
    int g = lane >> 2, t = lane & 3;
    int n0 = blockIdx.x * 128, m0 = blockIdx.y * 128;

    float acc[4][4][4];
#pragma unroll
    for (int i = 0; i < 4; i++)
#pragma unroll
        for (int j = 0; j < 4; j++)
#pragma unroll
            for (int q = 0; q < 4; q++) acc[i][j][q] = 0.f;

    const int nk = K >> 5;

    auto load_stage = [&](int s, int kc) {
        int k0 = kc << 5;
#pragma unroll
        for (int i = 0; i < 4; i++) {
            int idx = tid + i * 256;
            int r = idx >> 3, c = (idx & 7) * 4;
            uint32_t so = (uint32_t)((r * SSTRIDE + c) * 4);
            CP16(sb   + s * STAGE_BYTES + so, A  + (size_t)(m0 + r) * K + k0 + c);
            CP16(sb_B + s * STAGE_BYTES + so, Bt + (size_t)(n0 + r) * K + k0 + c);
        }
        CP_COMMIT();
    };

    load_stage(0, 0);
    load_stage(1, 1);
    load_stage(2, 2);

    const uint32_t* Asm = (const uint32_t*)smem;
    const uint32_t* Bsm = (const uint32_t*)(smem + NSTAGE * STAGE_BYTES);
    const int arow = warp_m * 64 + g;
    const int brow = warp_n * 32 + g;

    for (int kc = 0; kc < nk; kc++) {
        int buf = kc % NSTAGE;
        CP_WAIT(2);
        __syncthreads();

        const uint32_t* As_ = Asm + buf * (STAGE_BYTES / 4);
        const uint32_t* Bs_ = Bsm + buf * (STAGE_BYTES / 4);
#pragma unroll
        for (int ks = 0; ks < 4; ks++) {
            int k = ks * 8;
            uint32_t a[4][4], b[4][2];
#pragma unroll
            for (int i = 0; i < 4; i++) {
                int r = (arow + i * 16) * SSTRIDE + k + t;
                a[i][0] = As_[r];
                a[i][1] = As_[r + 8 * SSTRIDE];
                a[i][2] = As_[r + 4];
                a[i][3] = As_[r + 8 * SSTRIDE + 4];
            }
#pragma unroll
            for (int j = 0; j < 4; j++) {
                int r = (brow + j * 8) * SSTRIDE + k + t;
                b[j][0] = Bs_[r];
                b[j][1] = Bs_[r + 4];
            }
#pragma unroll
            for (int i = 0; i < 4; i++)
#pragma unroll
                for (int j = 0; j < 4; j++)
                    mma1688(acc[i][j], a[i], b[j]);
        }
        __syncthreads();
        if (kc + NSTAGE < nk) load_stage(buf, kc + NSTAGE);
        else CP_COMMIT();
    }

#pragma unroll
    for (int i = 0; i < 4; i++) {
        int m = m0 + warp_m * 64 + i * 16 + g;
#pragma unroll
        for (int j = 0; j < 4; j++) {
            int n = n0 + warp_n * 32 + j * 8 + t * 2;
            float b0 = bias[n], b1 = bias[n + 1];
            float v0 = acc[i][j][0] + b0, v1 = acc[i][j][1] + b1;
            float v2 = acc[i][j][2] + b0, v3 = acc[i][j][3] + b1;
            if (relu) {
                v0 = to_tf32(fmaxf(v0, 0.f)); v1 = to_tf32(fmaxf(v1, 0.f));
                v2 = to_tf32(fmaxf(v2, 0.f)); v3 = to_tf32(fmaxf(v3, 0.f));
            }
            size_t go0 = (size_t)m * N + n;
            size_t go1 = (size_t)(m + 8) * N + n;
            if (resid) {
                float2 r0 = *(const float2*)(resid + go0);
                float2 r1 = *(const float2*)(resid + go1);
                v0 += r0.x; v1 += r0.y; v2 += r1.x; v3 += r1.y;
            }
            *(float2*)(C + go0) = make_float2(v0, v1);
            *(float2*)(C + go1) = make_float2(v2, v3);
        }
    }
}

// ---------------------------------------------------------------------------
// Flash attention with tf32 mma.sync.
// Grid (T/64, NH, B). 128 threads = 4 warps; warp w owns q-rows w*16..w*16+15.
// BR=BC=64. Q frags in registers; K cp.async'd; V loaded transposed;
// P staged through warp-private smem (aliases Q staging region).
// Smem: Ks[64][68] | Vt[64][68] | Qs/Ps[64][68]  = 52224 bytes.
// ---------------------------------------------------------------------------
#define FSTR 68
#define FLASH_SMEM (3 * 64 * FSTR * 4)

__global__ void __launch_bounds__(128, 2) flash_kernel(
    const float* __restrict__ qkv, float* __restrict__ y)
{
    extern __shared__ float fs[];
    float* Ks = fs;
    float* Vt = fs + 64 * FSTR;
    float* Qs = fs + 2 * 64 * FSTR;

    int tid = threadIdx.x, w = tid >> 5, lane = tid & 31;
    int g = lane >> 2, t = lane & 3;
    int qt = blockIdx.x, h = blockIdx.y, b = blockIdx.z;
    int q0 = qt * 64;
    const float* base = qkv + (size_t)b * Tseq * 3072;
    const uint32_t sKs = smem_u32(Ks);

    // Load Q tile (coalesced), then hoist fragments to registers.
#pragma unroll
    for (int i = 0; i < 8; i++) {
        int idx = tid + i * 128;
        int row = idx >> 4, c4 = idx & 15;
        *(float4*)&Qs[row * FSTR + c4 * 4] =
            *(const float4*)(base + (size_t)(q0 + row) * 3072 + h * HD + c4 * 4);
    }
    __syncthreads();

    uint32_t qa[8][4];
    {
        const float* Qw = Qs + w * 16 * FSTR;
#pragma unroll
        for (int ks = 0; ks < 8; ks++) {
            int kk = ks * 8;
            qa[ks][0] = __float_as_uint(Qw[g * FSTR + kk + t]);
            qa[ks][1] = __float_as_uint(Qw[(g + 8) * FSTR + kk + t]);
            qa[ks][2] = __float_as_uint(Qw[g * FSTR + kk + t + 4]);
            qa[ks][3] = __float_as_uint(Qw[(g + 8) * FSTR + kk + t + 4]);
        }
    }
    float* Ps = Qs + w * 16 * FSTR;   // warp-private 16x68 region

    float m0 = -1e30f, l0 = 0.f, m1 = -1e30f, l1 = 0.f;
    float o[8][4];
#pragma unroll
    for (int j = 0; j < 8; j++)
#pragma unroll
        for (int q = 0; q < 4; q++) o[j][q] = 0.f;

    const int qrow0 = q0 + w * 16 + g;

    for (int kt = 0; kt <= qt; kt++) {
        int k0 = kt * 64;
        __syncthreads();   // Ks/Vt reusable (prev tile consumed by all warps)

        // K tile via cp.async, V tile transposed via LDG+STS
#pragma unroll
        for (int i = 0; i < 8; i++) {
            int idx = tid + i * 128;
            int row = idx >> 4, c4 = idx & 15;
            CP16(sKs + (uint32_t)(row * FSTR + c4 * 4) * 4,
                 base + (size_t)(k0 + row) * 3072 + Cemb + h * HD + c4 * 4);
        }
        CP_COMMIT();
#pragma unroll
        for (int i = 0; i < 8; i++) {
            int idx = tid + i * 128;
            int row = idx >> 4, c4 = idx & 15;
            float4 v = *(const float4*)(base + (size_t)(k0 + row) * 3072
                                        + 2 * Cemb + h * HD + c4 * 4);
            Vt[(c4 * 4 + 0) * FSTR + row] = v.x;
            Vt[(c4 * 4 + 1) * FSTR + row] = v.y;
            Vt[(c4 * 4 + 2) * FSTR + row] = v.z;
            Vt[(c4 * 4 + 3) * FSTR + row] = v.w;
        }
        CP_WAIT(0);
        __syncthreads();

        // S = Q @ K^T  (8 n-tiles x 8 k-steps)
        float s[8][4];
#pragma unroll
        for (int j = 0; j < 8; j++)
#pragma unroll
            for (int q = 0; q < 4; q++) s[j][q] = 0.f;
#pragma unroll
        for (int ks = 0; ks < 8; ks++) {
            int kk = ks * 8;
#pragma unroll
            for (int j = 0; j < 8; j++) {
                uint32_t kb[2];
                kb[0] = __float_as_uint(Ks[(j * 8 + g) * FSTR + kk + t]);
                kb[1] = __float_as_uint(Ks[(j * 8 + g) * FSTR + kk + t + 4]);
                mma1688(s[j], qa[ks], kb);
            }
        }

        // mask + online softmax  (scale = 1/sqrt(Cemb) = 1/32)
        const float sc = 0.03125f;
        float mt0 = -1e30f, mt1 = -1e30f;
        bool diag = (kt == qt);
#pragma unroll
        for (int j = 0; j < 8; j++) {
            int cb = k0 + j * 8 + t * 2;
            if (diag) {
                s[j][0] = (cb     <= qrow0)     ? s[j][0] * sc : -1e30f;
                s[j][1] = (cb + 1 <= qrow0)     ? s[j][1] * sc : -1e30f;
                s[j][2] = (cb     <= qrow0 + 8) ? s[j][2] * sc : -1e30f;
                s[j][3] = (cb + 1 <= qrow0 + 8) ? s[j][3] * sc : -1e30f;
            } else {
                s[j][0] *= sc; s[j][1] *= sc; s[j][2] *= sc; s[j][3] *= sc;
            }
            mt0 = fmaxf(mt0, fmaxf(s[j][0], s[j][1]));
            mt1 = fmaxf(mt1, fmaxf(s[j][2], s[j][3]));
        }
        mt0 = fmaxf(mt0, __shfl_xor_sync(~0u, mt0, 1));
        mt0 = fmaxf(mt0, __shfl_xor_sync(~0u, mt0, 2));
        mt1 = fmaxf(mt1, __shfl_xor_sync(~0u, mt1, 1));
        mt1 = fmaxf(mt1, __shfl_xor_sync(~0u, mt1, 2));

        float mn0 = fmaxf(m0, mt0), mn1 = fmaxf(m1, mt1);
        float cr0 = __expf(m0 - mn0), cr1 = __expf(m1 - mn1);
        float ls0 = 0.f, ls1 = 0.f;
#pragma unroll
        for (int j = 0; j < 8; j++) {
            float p0 = __expf(s[j][0] - mn0), p1 = __expf(s[j][1] - mn0);
            float p2 = __expf(s[j][2] - mn1), p3 = __expf(s[j][3] - mn1);
            ls0 += p0 + p1; ls1 += p2 + p3;
            int cl = j * 8 + t * 2;
            Ps[g * FSTR + cl]           = p0;
            Ps[g * FSTR + cl + 1]       = p1;
            Ps[(g + 8) * FSTR + cl]     = p2;
            Ps[(g + 8) * FSTR + cl + 1] = p3;
        }
        ls0 += __shfl_xor_sync(~0u, ls0, 1);
        ls0 += __shfl_xor_sync(~0u, ls0, 2);
        ls1 += __shfl_xor_sync(~0u, ls1, 1);
        ls1 += __shfl_xor_sync(~0u, ls1, 2);
        l0 = l0 * cr0 + ls0;
        l1 = l1 * cr1 + ls1;
        m0 = mn0; m1 = mn1;
#pragma unroll
        for (int j = 0; j < 8; j++) {
            o[j][0] *= cr0; o[j][1] *= cr0;
            o[j][2] *= cr1; o[j][3] *= cr1;
        }
        __syncwarp();

        // O += P @ V
#pragma unroll
        for (int ks = 0; ks < 8; ks++) {
            int kk = ks * 8;
            uint32_t pa[4];
            pa[0] = __float_as_uint(Ps[g * FSTR + kk + t]);
            pa[1] = __float_as_uint(Ps[(g + 8) * FSTR + kk + t]);
            pa[2] = __float_as_uint(Ps[g * FSTR + kk + t + 4]);
            pa[3] = __float_as_uint(Ps[(g + 8) * FSTR + kk + t + 4]);
#pragma unroll
            for (int j = 0; j < 8; j++) {
                uint32_t vb[2];
                vb[0] = __float_as_uint(Vt[(j * 8 + g) * FSTR + kk + t]);
                vb[1] = __float_as_uint(Vt[(j * 8 + g) * FSTR + kk + t + 4]);
                mma1688(o[j], pa, vb);
            }
        }
    }

    float il0 = 1.f / l0, il1 = 1.f / l1;
#pragma unroll
    for (int j = 0; j < 8; j++) {
        int col = h * HD + j * 8 + t * 2;
        size_t r0 = (size_t)(b * Tseq + qrow0) * Cemb + col;
        size_t r1 = (size_t)(b * Tseq + qrow0 + 8) * Cemb + col;
        y[r0]     = to_tf32(o[j][0] * il0);
        y[r0 + 1] = to_tf32(o[j][1] * il0);
        y[r1]     = to_tf32(o[j][2] * il1);
        y[r1 + 1] = to_tf32(o[j][3] * il1);
    }
}

// ---------------------------------------------------------------------------
// Launch
// ---------------------------------------------------------------------------
extern "C" void kernel_launch(void* const* d_in, const int* in_sizes, int n_in,
                              void* d_out, int out_size)
{
    (void)in_sizes; (void)n_in; (void)out_size;
    const float* x      = (const float*)d_in[0];
    const float* ln1_w  = (const float*)d_in[1];
    const float* ln1_b  = (const float*)d_in[2];
    const float* qkv_w  = (const float*)d_in[3];
    const float* qkv_b  = (const float*)d_in[4];
    const float* proj_w = (const float*)d_in[5];
    const float* proj_b = (const float*)d_in[6];
    const float* ln2_w  = (const float*)d_in[7];
    const float* ln2_b  = (const float*)d_in[8];
    const float* ff_w1  = (const float*)d_in[9];
    const float* ff_b1  = (const float*)d_in[10];
    const float* ff_w2  = (const float*)d_in[11];
    const float* ff_b2  = (const float*)d_in[12];
    float* out = (float*)d_out;

    float *ph, *pqkv, *py, *pff, *twq, *twp, *tw1, *tw2;
    cudaGetSymbolAddress((void**)&ph,   g_h);
    cudaGetSymbolAddress((void**)&pqkv, g_qkv);
    cudaGetSymbolAddress((void**)&py,   g_y);
    cudaGetSymbolAddress((void**)&pff,  g_ff);
    cudaGetSymbolAddress((void**)&twq,  g_wt_qkv);
    cudaGetSymbolAddress((void**)&twp,  g_wt_proj);
    cudaGetSymbolAddress((void**)&tw1,  g_wt_ff1);
    cudaGetSymbolAddress((void**)&tw2,  g_wt_ff2);

    cudaFuncSetAttribute(tgemm_kernel,
                         cudaFuncAttributeMaxDynamicSharedMemorySize, GSMEM_BYTES);
    cudaFuncSetAttribute(flash_kernel,
                         cudaFuncAttributeMaxDynamicSharedMemorySize, FLASH_SMEM);

    dim3 tb(32, 8);
    transpose_kernel<<<dim3(Cemb / 32, 3 * Cemb / 32), tb>>>(qkv_w, twq, Cemb, 3 * Cemb);
    transpose_kernel<<<dim3(Cemb / 32, Cemb / 32),     tb>>>(proj_w, twp, Cemb, Cemb);
    transpose_kernel<<<dim3(Cemb / 32, 4 * Cemb / 32), tb>>>(ff_w1, tw1, Cemb, 4 * Cemb);
    transpose_kernel<<<dim3(4 * Cemb / 32, Cemb / 32), tb>>>(ff_w2, tw2, 4 * Cemb, Cemb);

    // 1) h = LN1(x)
    ln_kernel<<<NTOK, 256>>>(x, ln1_w, ln1_b, ph);
    // 2) qkv = h @ qkv_w + qkv_b
    tgemm_kernel<<<dim3(3072 / 128, NTOK / 128), 256, GSMEM_BYTES>>>(
        ph, twq, qkv_b, nullptr, pqkv, NTOK, 3072, 1024, 0);
    // 3) y = attention(q, k, v)
    flash_kernel<<<dim3(Tseq / 64, NH, Bsz), 128, FLASH_SMEM>>>(pqkv, py);
    // 4) x2 = x + y @ proj_w + proj_b
    tgemm_kernel<<<dim3(1024 / 128, NTOK / 128), 256, GSMEM_BYTES>>>(
        py, twp, proj_b, x, out, NTOK, 1024, 1024, 0);
    // 5) h2 = LN2(x2)
    ln_kernel<<<NTOK, 256>>>(out, ln2_w, ln2_b, ph);
    // 6) ff = relu(h2 @ ff_w1 + ff_b1)
    tgemm_kernel<<<dim3(4096 / 128, NTOK / 128), 256, GSMEM_BYTES>>>(
        ph, tw1, ff_b1, nullptr, pff, NTOK, 4096, 1024, 1);
    // 7) out = x2 + ff @ ff_w2 + ff_b2
    tgemm_kernel<<<dim3(1024 / 128, NTOK / 128), 256, GSMEM_BYTES>>>(
        pff, tw2, ff_b2, out, out, NTOK, 1024, 4096, 0);
}

// round 5
// speedup vs baseline: 8.1995x; 2.1205x over previous
#include <cuda_runtime.h>
#include <cuda_fp16.h>
#include <cstdint>

#define Bsz  4
#define Tseq 2048
#define Cemb 1024
#define NH   16
#define HD   64
#define NTOK (Bsz * Tseq)   // 8192

// ---------------------------------------------------------------------------
// Scratch (static device globals — no runtime allocation)
// ---------------------------------------------------------------------------
__device__ __half g_h[NTOK * Cemb];            // LN output (half)
__device__ __half g_qkv[NTOK * 3 * Cemb];      // QKV (half)
__device__ __half g_yh[NTOK * Cemb];           // attention out (half)
__device__ __half g_ffh[NTOK * 4 * Cemb];      // FF1 out (half)
__device__ __half g_wt_qkv[3 * Cemb * Cemb];   // transposed weights (half)
__device__ __half g_wt_proj[Cemb * Cemb];
__device__ __half g_wt_ff1[4 * Cemb * Cemb];
__device__ __half g_wt_ff2[Cemb * 4 * Cemb];

// ---------------------------------------------------------------------------
// Helpers
// ---------------------------------------------------------------------------
__device__ __forceinline__ uint32_t smem_u32(const void* p) {
    uint32_t a;
    asm("{ .reg .u64 t; cvta.to.shared.u64 t, %1; cvt.u32.u64 %0, t; }"
        : "=r"(a) : "l"(p));
    return a;
}

#define CP16(sa, gp) \
    asm volatile("cp.async.cg.shared.global [%0], [%1], 16;" :: "r"(sa), "l"(gp))
#define CP_COMMIT() asm volatile("cp.async.commit_group;" ::: "memory")
#define CP_WAIT(n)  asm volatile("cp.async.wait_group %0;" :: "n"(n) : "memory")

#define LDSM4(R0, R1, R2, R3, ADDR) \
    asm volatile("ldmatrix.sync.aligned.m8n8.x4.shared.b16 {%0,%1,%2,%3}, [%4];" \
        : "=r"(R0), "=r"(R1), "=r"(R2), "=r"(R3) : "r"(ADDR))
#define LDSM4T(R0, R1, R2, R3, ADDR) \
    asm volatile("ldmatrix.sync.aligned.m8n8.x4.trans.shared.b16 {%0,%1,%2,%3}, [%4];" \
        : "=r"(R0), "=r"(R1), "=r"(R2), "=r"(R3) : "r"(ADDR))

__device__ __forceinline__ void mma16816(float* c, const uint32_t* a, const uint32_t* b) {
    asm volatile(
        "mma.sync.aligned.m16n8k16.row.col.f32.f16.f16.f32 "
        "{%0,%1,%2,%3}, {%4,%5,%6,%7}, {%8,%9}, {%0,%1,%2,%3};"
        : "+f"(c[0]), "+f"(c[1]), "+f"(c[2]), "+f"(c[3])
        : "r"(a[0]), "r"(a[1]), "r"(a[2]), "r"(a[3]), "r"(b[0]), "r"(b[1]));
}

// ---------------------------------------------------------------------------
// Weight transpose: W[K,N] (f32) -> Wt[N,K] (half)
// ---------------------------------------------------------------------------
__global__ __launch_bounds__(256) void transpose_kernel(
    const float* __restrict__ W, __half* __restrict__ Wt, int K, int N)
{
    __shared__ float t[32][33];
    int k0 = blockIdx.x * 32, n0 = blockIdx.y * 32;
    int tx = threadIdx.x, ty = threadIdx.y;
#pragma unroll
    for (int i = 0; i < 4; i++)
        t[ty + i * 8][tx] = W[(size_t)(k0 + ty + i * 8) * N + n0 + tx];
    __syncthreads();
#pragma unroll
    for (int i = 0; i < 4; i++)
        Wt[(size_t)(n0 + ty + i * 8) * K + k0 + tx] = __float2half_rn(t[tx][ty + i * 8]);
}

// ---------------------------------------------------------------------------
// LayerNorm: f32 in, half out
// ---------------------------------------------------------------------------
__global__ __launch_bounds__(256) void ln_kernel(
    const float* __restrict__ x, const float* __restrict__ w,
    const float* __restrict__ b, __half* __restrict__ out)
{
    __shared__ float red[64];
    int row = blockIdx.x;
    int tid = threadIdx.x;
    const float* xr = x + (size_t)row * Cemb;

    float v[4];
    float s = 0.f, s2 = 0.f;
#pragma unroll
    for (int i = 0; i < 4; i++) {
        v[i] = xr[i * 256 + tid];
        s  += v[i];
        s2 += v[i] * v[i];
    }
#pragma unroll
    for (int o = 16; o; o >>= 1) {
        s  += __shfl_xor_sync(~0u, s,  o);
        s2 += __shfl_xor_sync(~0u, s2, o);
    }
    int warp = tid >> 5, lane = tid & 31;
    if (lane == 0) { red[warp] = s; red[warp + 8] = s2; }
    __syncthreads();
    if (tid < 32) {
        float a  = (tid < 8) ? red[tid]     : 0.f;
        float a2 = (tid < 8) ? red[tid + 8] : 0.f;
#pragma unroll
        for (int o = 4; o; o >>= 1) {
            a  += __shfl_xor_sync(~0u, a,  o);
            a2 += __shfl_xor_sync(~0u, a2, o);
        }
        if (tid == 0) { red[0] = a; red[1] = a2; }
    }
    __syncthreads();
    float mean = red[0] * (1.f / Cemb);
    float var  = red[1] * (1.f / Cemb) - mean * mean;
    float rstd = rsqrtf(var + 1e-5f);
#pragma unroll
    for (int i = 0; i < 4; i++) {
        int c = i * 256 + tid;
        out[(size_t)row * Cemb + c] = __float2half_rn((v[i] - mean) * rstd * w[c] + b[c]);
    }
}

// ---------------------------------------------------------------------------
// fp16 mma.sync GEMM: C = A[M,K] @ Bt[N,K]^T + bias (+relu) (+resid)
// BM=128, BN=128, BK=64 halves. 256 threads = 8 warps (2M x 4N),
// warp tile 64x32 = 4x4 m16n8k16. 3-stage cp.async. ldmatrix fragments.
// smem rows: 72 halves (144B) -> ldmatrix conflict-free (16B/row phase shift).
// Output: half (Ch) if given, else float (Cf) with optional residual.
// ---------------------------------------------------------------------------
#define SSTRH 72
#define STAGE_B (128 * SSTRH * 2)   // 18432 bytes
#define NST 3
#define GSMEM_BYTES (2 * NST * STAGE_B)  // 110592

__global__ __launch_bounds__(256) void hgemm_kernel(
    const __half* __restrict__ A, const __half* __restrict__ Bt,
    const float* __restrict__ bias, const float* resid,
    float* Cf, __half* Ch, int M, int N, int K, int relu)
{
    extern __shared__ char smem[];
    const uint32_t sbA = smem_u32(smem);
    const uint32_t sbB = sbA + NST * STAGE_B;

    int tid = threadIdx.x, wid = tid >> 5, lane = tid & 31;
    int warp_m = wid >> 2, warp_n = wid & 3;
    int g = lane >> 2, t = lane & 3;
    int n0 = blockIdx.x * 128, m0 = blockIdx.y * 128;

    // ldmatrix lane-derived offsets
    int la  = lane & 15, ka8 = (lane >> 4) * 8;     // A-frag rows / k-half sel
    int lb  = lane & 7;
    int quad = lane >> 3;
    int jsel = quad >> 1, kb8 = (quad & 1) * 8;     // B-frag pair select

    float acc[4][4][4];
#pragma unroll
    for (int i = 0; i < 4; i++)
#pragma unroll
        for (int j = 0; j < 4; j++)
#pragma unroll
            for (int q = 0; q < 4; q++) acc[i][j][q] = 0.f;

    const int nk = K >> 6;  // BK=64

    auto load_stage = [&](int s, int kc) {
        int k0 = kc << 6;
#pragma unroll
        for (int i = 0; i < 4; i++) {
            int idx = tid + i * 256;
            int r = idx >> 3, c = idx & 7;
            uint32_t so = (uint32_t)(r * 144 + c * 16);
            CP16(sbA + s * STAGE_B + so, A  + (size_t)(m0 + r) * K + k0 + c * 8);
            CP16(sbB + s * STAGE_B + so, Bt + (size_t)(n0 + r) * K + k0 + c * 8);
        }
        CP_COMMIT();
    };

    load_stage(0, 0);
    load_stage(1, 1);
    load_stage(2, 2);

    for (int kc = 0; kc < nk; kc++) {
        int buf = kc % NST;
        CP_WAIT(2);
        __syncthreads();

        uint32_t Ab = sbA + buf * STAGE_B;
        uint32_t Bb = sbB + buf * STAGE_B;
#pragma unroll
        for (int ks = 0; ks < 4; ks++) {
            int kk = ks * 16;
            uint32_t a[4][4], bf[4][2];
#pragma unroll
            for (int i = 0; i < 4; i++)
                LDSM4(a[i][0], a[i][1], a[i][2], a[i][3],
                      Ab + (uint32_t)((warp_m * 64 + i * 16 + la) * 144 + (kk + ka8) * 2));
#pragma unroll
            for (int jp = 0; jp < 2; jp++) {
                uint32_t r0, r1, r2, r3;
                LDSM4(r0, r1, r2, r3,
                      Bb + (uint32_t)((warp_n * 32 + (jp * 2 + jsel) * 8 + lb) * 144
                                      + (kk + kb8) * 2));
                bf[jp * 2][0] = r0; bf[jp * 2][1] = r1;
                bf[jp * 2 + 1][0] = r2; bf[jp * 2 + 1][1] = r3;
            }
#pragma unroll
            for (int i = 0; i < 4; i++)
#pragma unroll
                for (int j = 0; j < 4; j++)
                    mma16816(acc[i][j], a[i], bf[j]);
        }
        __syncthreads();
        if (kc + NST < nk) load_stage(buf, kc + NST);
        else CP_COMMIT();
    }

    // ---- epilogue ----
#pragma unroll
    for (int i = 0; i < 4; i++) {
        int m = m0 + warp_m * 64 + i * 16 + g;
#pragma unroll
        for (int j = 0; j < 4; j++) {
            int n = n0 + warp_n * 32 + j * 8 + t * 2;
            float b0 = bias[n], b1 = bias[n + 1];
            float v0 = acc[i][j][0] + b0, v1 = acc[i][j][1] + b1;
            float v2 = acc[i][j][2] + b0, v3 = acc[i][j][3] + b1;
            if (relu) {
                v0 = fmaxf(v0, 0.f); v1 = fmaxf(v1, 0.f);
                v2 = fmaxf(v2, 0.f); v3 = fmaxf(v3, 0.f);
            }
            size_t go0 = (size_t)m * N + n;
            size_t go1 = (size_t)(m + 8) * N + n;
            if (Ch) {
                *(__half2*)(Ch + go0) = __floats2half2_rn(v0, v1);
                *(__half2*)(Ch + go1) = __floats2half2_rn(v2, v3);
            } else {
                if (resid) {
                    float2 r0 = *(const float2*)(resid + go0);
                    float2 r1 = *(const float2*)(resid + go1);
                    v0 += r0.x; v1 += r0.y; v2 += r1.x; v3 += r1.y;
                }
                *(float2*)(Cf + go0) = make_float2(v0, v1);
                *(float2*)(Cf + go1) = make_float2(v2, v3);
            }
        }
    }
}

// ---------------------------------------------------------------------------
// Flash attention, fp16 mma m16n8k16.
// Grid (T/64, NH, B). 128 threads = 4 warps; warp w owns q-rows w*16..+15.
// Ks/Vs seq-major [64][72] halves; Vs B-frags via ldmatrix.trans.
// Q frags hoisted; P staged in warp-private slice of the Q smem region.
// ---------------------------------------------------------------------------
#define FST 72
#define FLASH_SMEM (3 * 64 * FST * 2)   // 27648

__global__ void __launch_bounds__(128) flash_kernel(
    const __half* __restrict__ qkv, __half* __restrict__ y)
{
    extern __shared__ __half fsm[];
    __half* Ksp = fsm;
    __half* Vsp = fsm + 64 * FST;
    __half* Qsp = fsm + 2 * 64 * FST;
    const uint32_t sKs = smem_u32(Ksp);
    const uint32_t sVs = smem_u32(Vsp);
    const uint32_t sQs = smem_u32(Qsp);

    int tid = threadIdx.x, w = tid >> 5, lane = tid & 31;
    int g = lane >> 2, t = lane & 3;
    int la = lane & 15, ka8 = (lane >> 4) * 8;
    int lb = lane & 7;
    int quad = lane >> 3;
    int jsel = quad >> 1, kb8 = (quad & 1) * 8;
    int vrow = (quad & 1) * 8 + lb;                 // for ldmatrix.trans rows

    int qt = blockIdx.x, h = blockIdx.y, b = blockIdx.z;
    int q0 = qt * 64;
    const __half* base = qkv + (size_t)b * Tseq * 3072;

    // Q tile via cp.async
#pragma unroll
    for (int i = 0; i < 4; i++) {
        int idx = tid + i * 128;
        int r = idx >> 3, c = idx & 7;
        CP16(sQs + (uint32_t)(r * 144 + c * 16),
             base + (size_t)(q0 + r) * 3072 + h * HD + c * 8);
    }
    CP_COMMIT(); CP_WAIT(0);
    __syncthreads();

    uint32_t qa[4][4];
#pragma unroll
    for (int ks = 0; ks < 4; ks++)
        LDSM4(qa[ks][0], qa[ks][1], qa[ks][2], qa[ks][3],
              sQs + (uint32_t)((w * 16 + la) * 144 + (ks * 16 + ka8) * 2));

    __half* Psp = Qsp + w * 16 * FST;               // warp-private 16x72
    const uint32_t sPs = sQs + (uint32_t)(w * 16 * 144);

    float m0 = -1e30f, l0 = 0.f, m1 = -1e30f, l1 = 0.f;
    float o[8][4];
#pragma unroll
    for (int j = 0; j < 8; j++)
#pragma unroll
        for (int q = 0; q < 4; q++) o[j][q] = 0.f;

    const int qrow0 = q0 + w * 16 + g;

    for (int kt = 0; kt <= qt; kt++) {
        int k0 = kt * 64;
        __syncthreads();
#pragma unroll
        for (int i = 0; i < 4; i++) {
            int idx = tid + i * 128;
            int r = idx >> 3, c = idx & 7;
            uint32_t so = (uint32_t)(r * 144 + c * 16);
            const __half* kr = base + (size_t)(k0 + r) * 3072 + Cemb + h * HD + c * 8;
            CP16(sKs + so, kr);
            CP16(sVs + so, kr + Cemb);
        }
        CP_COMMIT(); CP_WAIT(0);
        __syncthreads();

        // S = Q @ K^T
        float s[8][4];
#pragma unroll
        for (int j = 0; j < 8; j++)
#pragma unroll
            for (int q = 0; q < 4; q++) s[j][q] = 0.f;
#pragma unroll
        for (int ks = 0; ks < 4; ks++) {
            int kk = ks * 16;
            uint32_t kb[8][2];
#pragma unroll
            for (int jp = 0; jp < 4; jp++) {
                uint32_t r0, r1, r2, r3;
                LDSM4(r0, r1, r2, r3,
                      sKs + (uint32_t)(((jp * 2 + jsel) * 8 + lb) * 144 + (kk + kb8) * 2));
                kb[jp * 2][0] = r0; kb[jp * 2][1] = r1;
                kb[jp * 2 + 1][0] = r2; kb[jp * 2 + 1][1] = r3;
            }
#pragma unroll
            for (int j = 0; j < 8; j++)
                mma16816(s[j], qa[ks], kb[j]);
        }

        // mask + online softmax (scale 1/sqrt(Cemb) = 1/32)
        const float sc = 0.03125f;
        float mt0 = -1e30f, mt1 = -1e30f;
        bool diag = (kt == qt);
#pragma unroll
        for (int j = 0; j < 8; j++) {
            int cb = k0 + j * 8 + t * 2;
            if (diag) {
                s[j][0] = (cb     <= qrow0)     ? s[j][0] * sc : -1e30f;
                s[j][1] = (cb + 1 <= qrow0)     ? s[j][1] * sc : -1e30f;
                s[j][2] = (cb     <= qrow0 + 8) ? s[j][2] * sc : -1e30f;
                s[j][3] = (cb + 1 <= qrow0 + 8) ? s[j][3] * sc : -1e30f;
            } else {
                s[j][0] *= sc; s[j][1] *= sc; s[j][2] *= sc; s[j][3] *= sc;
            }
            mt0 = fmaxf(mt0, fmaxf(s[j][0], s[j][1]));
            mt1 = fmaxf(mt1, fmaxf(s[j][2], s[j][3]));
        }
        mt0 = fmaxf(mt0, __shfl_xor_sync(~0u, mt0, 1));
        mt0 = fmaxf(mt0, __shfl_xor_sync(~0u, mt0, 2));
        mt1 = fmaxf(mt1, __shfl_xor_sync(~0u, mt1, 1));
        mt1 = fmaxf(mt1, __shfl_xor_sync(~0u, mt1, 2));

        float mn0 = fmaxf(m0, mt0), mn1 = fmaxf(m1, mt1);
        float cr0 = __expf(m0 - mn0), cr1 = __expf(m1 - mn1);
        float ls0 = 0.f, ls1 = 0.f;
#pragma unroll
        for (int j = 0; j < 8; j++) {
            float p0 = __expf(s[j][0] - mn0), p1 = __expf(s[j][1] - mn0);
            float p2 = __expf(s[j][2] - mn1), p3 = __expf(s[j][3] - mn1);
            ls0 += p0 + p1; ls1 += p2 + p3;
            int cl = j * 8 + t * 2;
            *(__half2*)(Psp + g * FST + cl)       = __floats2half2_rn(p0, p1);
            *(__half2*)(Psp + (g + 8) * FST + cl) = __floats2half2_rn(p2, p3);
        }
        ls0 += __shfl_xor_sync(~0u, ls0, 1);
        ls0 += __shfl_xor_sync(~0u, ls0, 2);
        ls1 += __shfl_xor_sync(~0u, ls1, 1);
        ls1 += __shfl_xor_sync(~0u, ls1, 2);
        l0 = l0 * cr0 + ls0;
        l1 = l1 * cr1 + ls1;
        m0 = mn0; m1 = mn1;
#pragma unroll
        for (int j = 0; j < 8; j++) {
            o[j][0] *= cr0; o[j][1] *= cr0;
            o[j][2] *= cr1; o[j][3] *= cr1;
        }
        __syncwarp();

        // O += P @ V   (V B-frags via ldmatrix.trans)
#pragma unroll
        for (int ks = 0; ks < 4; ks++) {
            int kk = ks * 16;
            uint32_t pa[4];
            LDSM4(pa[0], pa[1], pa[2], pa[3],
                  sPs + (uint32_t)(la * 144 + (kk + ka8) * 2));
            uint32_t vb[8][2];
#pragma unroll
            for (int jp = 0; jp < 4; jp++) {
                uint32_t r0, r1, r2, r3;
                LDSM4T(r0, r1, r2, r3,
                       sVs + (uint32_t)((kk + vrow) * 144 + (jp * 2 + jsel) * 16));
                vb[jp * 2][0] = r0; vb[jp * 2][1] = r1;
                vb[jp * 2 + 1][0] = r2; vb[jp * 2 + 1][1] = r3;
            }
#pragma unroll
            for (int j = 0; j < 8; j++)
                mma16816(o[j], pa, vb[j]);
        }
        __syncwarp();
    }

    float il0 = 1.f / l0, il1 = 1.f / l1;
#pragma unroll
    for (int j = 0; j < 8; j++) {
        int col = h * HD + j * 8 + t * 2;
        size_t r0 = (size_t)(b * Tseq + qrow0) * Cemb + col;
        size_t r1 = (size_t)(b * Tseq + qrow0 + 8) * Cemb + col;
        *(__half2*)(y + r0) = __floats2half2_rn(o[j][0] * il0, o[j][1] * il0);
        *(__half2*)(y + r1) = __floats2half2_rn(o[j][2] * il1, o[j][3] * il1);
    }
}

// ---------------------------------------------------------------------------
// Launch
// ---------------------------------------------------------------------------
extern "C" void kernel_launch(void* const* d_in, const int* in_sizes, int n_in,
                              void* d_out, int out_size)
{
    (void)in_sizes; (void)n_in; (void)out_size;
    const float* x      = (const float*)d_in[0];
    const float* ln1_w  = (const float*)d_in[1];
    const float* ln1_b  = (const float*)d_in[2];
    const float* qkv_w  = (const float*)d_in[3];
    const float* qkv_b  = (const float*)d_in[4];
    const float* proj_w = (const float*)d_in[5];
    const float* proj_b = (const float*)d_in[6];
    const float* ln2_w  = (const float*)d_in[7];
    const float* ln2_b  = (const float*)d_in[8];
    const float* ff_w1  = (const float*)d_in[9];
    const float* ff_b1  = (const float*)d_in[10];
    const float* ff_w2  = (const float*)d_in[11];
    const float* ff_b2  = (const float*)d_in[12];
    float* out = (float*)d_out;

    __half *ph, *pqkv, *py, *pff, *twq, *twp, *tw1, *tw2;
    cudaGetSymbolAddress((void**)&ph,   g_h);
    cudaGetSymbolAddress((void**)&pqkv, g_qkv);
    cudaGetSymbolAddress((void**)&py,   g_yh);
    cudaGetSymbolAddress((void**)&pff,  g_ffh);
    cudaGetSymbolAddress((void**)&twq,  g_wt_qkv);
    cudaGetSymbolAddress((void**)&twp,  g_wt_proj);
    cudaGetSymbolAddress((void**)&tw1,  g_wt_ff1);
    cudaGetSymbolAddress((void**)&tw2,  g_wt_ff2);

    cudaFuncSetAttribute(hgemm_kernel,
                         cudaFuncAttributeMaxDynamicSharedMemorySize, GSMEM_BYTES);
    cudaFuncSetAttribute(flash_kernel,
                         cudaFuncAttributeMaxDynamicSharedMemorySize, FLASH_SMEM);

    dim3 tb(32, 8);
    transpose_kernel<<<dim3(Cemb / 32, 3 * Cemb / 32), tb>>>(qkv_w, twq, Cemb, 3 * Cemb);
    transpose_kernel<<<dim3(Cemb / 32, Cemb / 32),     tb>>>(proj_w, twp, Cemb, Cemb);
    transpose_kernel<<<dim3(Cemb / 32, 4 * Cemb / 32), tb>>>(ff_w1, tw1, Cemb, 4 * Cemb);
    transpose_kernel<<<dim3(4 * Cemb / 32, Cemb / 32), tb>>>(ff_w2, tw2, 4 * Cemb, Cemb);

    // 1) h = LN1(x)
    ln_kernel<<<NTOK, 256>>>(x, ln1_w, ln1_b, ph);
    // 2) qkv = h @ qkv_w + qkv_b  (half out)
    hgemm_kernel<<<dim3(3072 / 128, NTOK / 128), 256, GSMEM_BYTES>>>(
        ph, twq, qkv_b, nullptr, nullptr, pqkv, NTOK, 3072, 1024, 0);
    // 3) y = attention(q, k, v)  (half out)
    flash_kernel<<<dim3(Tseq / 64, NH, Bsz), 128, FLASH_SMEM>>>(pqkv, py);
    // 4) x2 = x + y @ proj_w + proj_b  (float out)
    hgemm_kernel<<<dim3(1024 / 128, NTOK / 128), 256, GSMEM_BYTES>>>(
        py, twp, proj_b, x, out, nullptr, NTOK, 1024, 1024, 0);
    // 5) h2 = LN2(x2)
    ln_kernel<<<NTOK, 256>>>(out, ln2_w, ln2_b, ph);
    // 6) ff = relu(h2 @ ff_w1 + ff_b1)  (half out)
    hgemm_kernel<<<dim3(4096 / 128, NTOK / 128), 256, GSMEM_BYTES>>>(
        ph, tw1, ff_b1, nullptr, nullptr, pff, NTOK, 4096, 1024, 1);
    // 7) out = x2 + ff @ ff_w2 + ff_b2  (float out)
    hgemm_kernel<<<dim3(1024 / 128, NTOK / 128), 256, GSMEM_BYTES>>>(
        pff, tw2, ff_b2, out, out, nullptr, NTOK, 1024, 4096, 0);
}